// round 1
// baseline (speedup 1.0000x reference)
#include <cuda_runtime.h>
#include <math.h>

#define NPROP 1500
#define NACT 64
#define NCLS 81
#define PERSON_IDX 2
#define O_CHUNK 100          // 1500 / 15 chunks
#define THREADS 256

// per-proposal scratch (no cudaMalloc allowed)
__device__ float g_H[NPROP];     // humaness (0 unless person)
__device__ float g_O[NPROP];     // objectness (0 if person)
__device__ float g_cx[NPROP];
__device__ float g_cy[NPROP];
__device__ float g_iw[NPROP];    // 1/w
__device__ float g_ih[NPROP];    // 1/h
__device__ float g_lw[NPROP];    // log w
__device__ float g_lh[NPROP];    // log h

__global__ void prep_kernel(const float* __restrict__ scores,
                            const float* __restrict__ bbox) {
    int i = blockIdx.x * blockDim.x + threadIdx.x;
    if (i >= NPROP) return;

    // argmax over 81 classes (first occurrence on ties, matches jnp.argmax)
    const float* s = scores + i * NCLS;
    float best = s[0];
    int bi = 0;
    #pragma unroll 8
    for (int c = 1; c < NCLS; c++) {
        float v = s[c];
        if (v > best) { best = v; bi = c; }
    }
    g_H[i] = (bi == PERSON_IDX) ? best : 0.0f;
    g_O[i] = (bi == PERSON_IDX) ? 0.0f : best;

    float x0 = bbox[i * 4 + 0];
    float y0 = bbox[i * 4 + 1];
    float x1 = bbox[i * 4 + 2];
    float y1 = bbox[i * 4 + 3];
    float w = x1 - x0;
    float h = y1 - y0;
    g_cx[i] = x0 + 0.5f * w;
    g_cy[i] = y0 + 0.5f * h;
    g_iw[i] = 1.0f / w;
    g_ih[i] = 1.0f / h;
    g_lw[i] = logf(w);
    g_lh[i] = logf(h);
}

// out[h, o, a] = H[h]*O[o]*L[h,a]*exp(-( |enc-mu|^2 )*k)
//             = O[o] * (H*L*exp(-k*m2))[a] * exp( dot(enc, 2k*mu[a]) - k*e2 )
__global__ void __launch_bounds__(THREADS, 8)
score_kernel(const float* __restrict__ action_logits,
             const float* __restrict__ target_mean,
             float* __restrict__ out) {
    const int h  = blockIdx.y;
    const int o0 = blockIdx.x * O_CHUNK;
    const float H = g_H[h];

    float* blk_out = out + (size_t)h * (NPROP * NACT) + (size_t)o0 * NACT;

    if (H == 0.0f) {
        // pure zero-fill: O_CHUNK*64 floats = 1600 float4, STG.128 coalesced
        float4 z = make_float4(0.f, 0.f, 0.f, 0.f);
        float4* p = reinterpret_cast<float4*>(blk_out);
        #pragma unroll
        for (int i = threadIdx.x; i < (O_CHUNK * NACT) / 4; i += THREADS)
            p[i] = z;
        return;
    }

    const float K = 5.5555555555555554f;  // 1/(2*0.3^2)

    __shared__ float sM0[NACT], sM1[NACT], sM2[NACT], sM3[NACT];
    __shared__ float sHQ[NACT];

    int tid = threadIdx.x;
    if (tid < NACT) {
        const float* mu = target_mean + ((size_t)h * NACT + tid) * 4;
        float m0 = mu[0], m1 = mu[1], m2 = mu[2], m3 = mu[3];
        float msq = m0 * m0 + m1 * m1 + m2 * m2 + m3 * m3;
        float twoK = 2.0f * K;
        sM0[tid] = twoK * m0;
        sM1[tid] = twoK * m1;
        sM2[tid] = twoK * m2;
        sM3[tid] = twoK * m3;
        sHQ[tid] = H * action_logits[(size_t)h * NACT + tid] * __expf(-K * msq);
    }
    __syncthreads();

    const float cxh = g_cx[h], cyh = g_cy[h];
    const float iw = g_iw[h],  ih = g_ih[h];
    const float lw = g_lw[h],  lh = g_lh[h];

    const int a    = tid & (NACT - 1);
    const int osub = tid >> 6;              // 0..3
    const float M0 = sM0[a], M1 = sM1[a], M2 = sM2[a], M3 = sM3[a];
    const float HQ = sHQ[a];

    for (int o = o0 + osub; o < o0 + O_CHUNK; o += (THREADS / NACT)) {
        float Ov = g_O[o];
        float tx = (g_cx[o] - cxh) * iw;
        float ty = (g_cy[o] - cyh) * ih;
        float tw = g_lw[o] - lw;
        float th = g_lh[o] - lh;
        float e2 = tx * tx + ty * ty + tw * tw + th * th;
        float ex = fmaf(tx, M0, fmaf(ty, M1, fmaf(tw, M2, th * M3))) - K * e2;
        blk_out[(size_t)(o - o0) * NACT + a] = Ov * HQ * __expf(ex);
    }
}

extern "C" void kernel_launch(void* const* d_in, const int* in_sizes, int n_in,
                              void* d_out, int out_size) {
    const float* action_logits = (const float*)d_in[0];  // [1500,64]
    const float* target_mean   = (const float*)d_in[1];  // [1500,64,4]
    const float* bbox          = (const float*)d_in[2];  // [1500,4]
    const float* scores        = (const float*)d_in[3];  // [1500,81]
    float* out = (float*)d_out;                          // [1500,1500,64]

    prep_kernel<<<(NPROP + 127) / 128, 128>>>(scores, bbox);

    dim3 grid(NPROP / O_CHUNK, NPROP);  // (15, 1500)
    score_kernel<<<grid, THREADS>>>(action_logits, target_mean, out);
}

// round 2
// speedup vs baseline: 1.0898x; 1.0898x over previous
#include <cuda_runtime.h>
#include <math.h>

#define NPROP 1500
#define NACT 64
#define NCLS 81
#define PERSON_IDX 2
#define O_CHUNK 100          // 1500 / 15 chunks
#define THREADS 256

// Fully fused: every block derives what it needs from raw inputs.
// out[h, o, a] = H[h]*O[o]*L[h,a]*exp(-|enc-mu|^2 * k)
//             = O[o] * (H*L*exp(-k*|mu|^2))[a] * exp( dot(enc, 2k*mu[a]) - k*|enc|^2 )
__global__ void __launch_bounds__(THREADS, 8)
score_kernel(const float* __restrict__ action_logits,
             const float* __restrict__ target_mean,
             const float* __restrict__ bbox,
             const float* __restrict__ scores,
             float* __restrict__ out) {
    const int h  = blockIdx.y;
    const int o0 = blockIdx.x * O_CHUNK;
    const int tid = threadIdx.x;

    // ---- cooperative argmax over scores[h, 0..80] (first-index tie-break) ----
    __shared__ float sv[128];
    __shared__ int   si[128];
    if (tid < 128) {
        sv[tid] = (tid < NCLS) ? scores[(size_t)h * NCLS + tid] : -INFINITY;
        si[tid] = tid;
    }
    __syncthreads();
    #pragma unroll
    for (int s = 64; s > 0; s >>= 1) {
        if (tid < s) {
            float v2 = sv[tid + s];
            if (v2 > sv[tid] || (v2 == sv[tid] && si[tid + s] < si[tid])) {
                sv[tid] = v2; si[tid] = si[tid + s];
            }
        }
        __syncthreads();
    }
    const float H = (si[0] == PERSON_IDX) ? sv[0] : 0.0f;

    float* blk_out = out + (size_t)h * (NPROP * NACT) + (size_t)o0 * NACT;

    if (H == 0.0f) {
        // pure zero-fill: O_CHUNK*64 floats = 1600 float4, streaming STG.128
        float4 z = make_float4(0.f, 0.f, 0.f, 0.f);
        float4* p = reinterpret_cast<float4*>(blk_out);
        #pragma unroll
        for (int i = tid; i < (O_CHUNK * NACT) / 4; i += THREADS)
            __stcs(p + i, z);
        return;
    }

    // ---- rare person path (~1.2% of blocks) ----
    const float K = 5.5555555555555554f;  // 1/(2*0.3^2)

    __shared__ float sM0[NACT], sM1[NACT], sM2[NACT], sM3[NACT], sHQ[NACT];
    __shared__ float sOv[O_CHUNK], sOcx[O_CHUNK], sOcy[O_CHUNK];
    __shared__ float sOlw[O_CHUNK], sOlh[O_CHUNK];

    if (tid < NACT) {
        const float* mu = target_mean + ((size_t)h * NACT + tid) * 4;
        float m0 = mu[0], m1 = mu[1], m2 = mu[2], m3 = mu[3];
        float msq = m0 * m0 + m1 * m1 + m2 * m2 + m3 * m3;
        float twoK = 2.0f * K;
        sM0[tid] = twoK * m0;
        sM1[tid] = twoK * m1;
        sM2[tid] = twoK * m2;
        sM3[tid] = twoK * m3;
        sHQ[tid] = H * action_logits[(size_t)h * NACT + tid] * __expf(-K * msq);
    }

    // per-o stats into shared (100 threads, serial 81-class argmax each; L2-hit)
    for (int j = tid; j < O_CHUNK; j += THREADS) {
        int o = o0 + j;
        const float* s = scores + (size_t)o * NCLS;
        float best = s[0];
        int bi = 0;
        #pragma unroll 8
        for (int c = 1; c < NCLS; c++) {
            float v = s[c];
            if (v > best) { best = v; bi = c; }
        }
        sOv[j] = (bi == PERSON_IDX) ? 0.0f : best;

        float x0 = bbox[o * 4 + 0], y0 = bbox[o * 4 + 1];
        float x1 = bbox[o * 4 + 2], y1 = bbox[o * 4 + 3];
        float w = x1 - x0, hh = y1 - y0;
        sOcx[j] = x0 + 0.5f * w;
        sOcy[j] = y0 + 0.5f * hh;
        sOlw[j] = logf(w);
        sOlh[j] = logf(hh);
    }

    // h box stats (broadcast loads, every thread)
    float hx0 = bbox[h * 4 + 0], hy0 = bbox[h * 4 + 1];
    float hx1 = bbox[h * 4 + 2], hy1 = bbox[h * 4 + 3];
    float hw = hx1 - hx0, hhh = hy1 - hy0;
    const float cxh = hx0 + 0.5f * hw;
    const float cyh = hy0 + 0.5f * hhh;
    const float iw = 1.0f / hw, ih = 1.0f / hhh;
    const float lw = logf(hw), lh = logf(hhh);

    __syncthreads();

    const int a    = tid & (NACT - 1);
    const int osub = tid >> 6;              // 0..3
    const float M0 = sM0[a], M1 = sM1[a], M2 = sM2[a], M3 = sM3[a];
    const float HQ = sHQ[a];

    for (int j = osub; j < O_CHUNK; j += (THREADS / NACT)) {
        float Ov = sOv[j];
        float tx = (sOcx[j] - cxh) * iw;
        float ty = (sOcy[j] - cyh) * ih;
        float tw = sOlw[j] - lw;
        float th = sOlh[j] - lh;
        float e2 = tx * tx + ty * ty + tw * tw + th * th;
        float ex = fmaf(tx, M0, fmaf(ty, M1, fmaf(tw, M2, th * M3))) - K * e2;
        __stcs(blk_out + (size_t)j * NACT + a, Ov * HQ * __expf(ex));
    }
}

extern "C" void kernel_launch(void* const* d_in, const int* in_sizes, int n_in,
                              void* d_out, int out_size) {
    const float* action_logits = (const float*)d_in[0];  // [1500,64]
    const float* target_mean   = (const float*)d_in[1];  // [1500,64,4]
    const float* bbox          = (const float*)d_in[2];  // [1500,4]
    const float* scores        = (const float*)d_in[3];  // [1500,81]
    float* out = (float*)d_out;                          // [1500,1500,64]

    dim3 grid(NPROP / O_CHUNK, NPROP);  // (15, 1500)
    score_kernel<<<grid, THREADS>>>(action_logits, target_mean, bbox, scores, out);
}